// round 13
// baseline (speedup 1.0000x reference)
#include <cuda_runtime.h>

// cosine_regularizer: out = (sum(W) - N)/N^2, W = p p^T, p = row-normalized points.
// Identity: sum(W) = || sum_i p_i ||^2, and per column the atomic linearization
// telescopes:  sum_j (x_j^2 + 2 x_j * prefix_j) = (sum_j x_j)^2  for ANY order.
// R13: each block turns its column partials into an exact additive scalar share of
//      ||s||^2 using atomicAdd return values -> the finalize is one scalar read.
//      g_s columns padded to 128B lines so per-address serialization runs across
//      LTS slices in parallel.

constexpr int N_ROWS = 16384;
constexpr int D      = 256;
constexpr int TPB    = 256;                 // 8 warps
constexpr int WARPS  = TPB / 32;
constexpr int NBLK   = 512;                 // 512*8 warps * 4 rows = 16384 rows
constexpr int ROWS_PER_WARP = 4;

__device__ float        g_s[D][32];   // one 128B line per column; reset by last block
__device__ double       g_acc;        // scalar accumulator of ||s||^2 shares
__device__ unsigned int g_count;      // arrival counter

__global__ void __launch_bounds__(TPB, 3)
k_fused(const float* __restrict__ pts, float* __restrict__ out) {
    const int warp = threadIdx.x >> 5;
    const int lane = threadIdx.x & 31;
    const int t    = threadIdx.x;
    const int gw   = blockIdx.x * WARPS + warp;

    // Batch-issue all 8 LDG.128 for this warp's 4 rows.
    float4 v0[ROWS_PER_WARP], v1[ROWS_PER_WARP];
#pragma unroll
    for (int k = 0; k < ROWS_PER_WARP; k++) {
        const int row = gw + k * (NBLK * WARPS);
        const float4* p = reinterpret_cast<const float4*>(pts) + (size_t)row * (D / 4);
        v0[k] = p[lane];        // cols 4*lane   .. +3
        v1[k] = p[32 + lane];   // cols 128+4*lane .. +3
    }

    // Per-row sum of squares; 4 interleaved warp reductions.
    float ss[ROWS_PER_WARP];
#pragma unroll
    for (int k = 0; k < ROWS_PER_WARP; k++) {
        ss[k] = v0[k].x * v0[k].x + v0[k].y * v0[k].y + v0[k].z * v0[k].z + v0[k].w * v0[k].w
              + v1[k].x * v1[k].x + v1[k].y * v1[k].y + v1[k].z * v1[k].z + v1[k].w * v1[k].w;
    }
#pragma unroll
    for (int off = 16; off > 0; off >>= 1) {
#pragma unroll
        for (int k = 0; k < ROWS_PER_WARP; k++)
            ss[k] += __shfl_xor_sync(0xffffffffu, ss[k], off);
    }

    // rnorm * row into per-lane column accumulators.
    float4 a0 = make_float4(0.f, 0.f, 0.f, 0.f);
    float4 a1 = make_float4(0.f, 0.f, 0.f, 0.f);
#pragma unroll
    for (int k = 0; k < ROWS_PER_WARP; k++) {
        const float rn = rsqrtf(ss[k]);
        a0.x += rn * v0[k].x;  a0.y += rn * v0[k].y;
        a0.z += rn * v0[k].z;  a0.w += rn * v0[k].w;
        a1.x += rn * v1[k].x;  a1.y += rn * v1[k].y;
        a1.z += rn * v1[k].z;  a1.w += rn * v1[k].w;
    }

    // Block-reduce 8 warps' column partials via shared.
    __shared__ float sh[WARPS][D];
    float4* shv = reinterpret_cast<float4*>(sh[warp]);
    shv[lane]      = a0;
    shv[32 + lane] = a1;
    __syncthreads();

    float s = sh[0][t];
#pragma unroll
    for (int w = 1; w < WARPS; w++) s += sh[w][t];

    // Telescoping share: old = running prefix for this column (any order works).
    const float old = atomicAdd(&g_s[t][0], s);
    double term = (double)s * ((double)s + 2.0 * (double)old);

    // Block-reduce the 256 per-column terms (double) -> one scalar share.
#pragma unroll
    for (int off = 16; off > 0; off >>= 1)
        term += __shfl_xor_sync(0xffffffffu, term, off);
    __shared__ double wsum[WARPS];
    if (lane == 0) wsum[warp] = term;
    __syncthreads();

    __shared__ unsigned int s_isLast;
    if (warp == 0) {
        double x = (lane < WARPS) ? wsum[lane] : 0.0;
#pragma unroll
        for (int off = 4; off > 0; off >>= 1)
            x += __shfl_xor_sync(0xffffffffu, x, off);
        if (lane == 0) {
            atomicAdd(&g_acc, x);    // relaxed scalar accumulation
            // Release-arrive: our g_acc add (and g_s atomics) precede the count.
            unsigned int oldc;
            asm volatile("atom.release.gpu.global.add.u32 %0, [%1], 1;"
                         : "=r"(oldc) : "l"(&g_count) : "memory");
            s_isLast = (oldc == (unsigned int)(NBLK - 1)) ? 1u : 0u;
        }
    }
    __syncthreads();
    if (!s_isLast) return;

    // Last block: acquire pairs with all releases; g_acc is complete.
    g_s[t][0] = 0.0f;                       // reset column prefixes for next replay
    if (t == 0) {
        unsigned int dummy;
        asm volatile("atom.acquire.gpu.global.add.u32 %0, [%1], 0;"
                     : "=r"(dummy) : "l"(&g_count) : "memory");
        const double acc = __ldcg(&g_acc);
        const double n = (double)N_ROWS;
        out[0] = (float)((acc - n) / (n * n));
        g_acc   = 0.0;                      // reset for next replay
        g_count = 0u;
    }
}

extern "C" void kernel_launch(void* const* d_in, const int* in_sizes, int n_in,
                              void* d_out, int out_size) {
    const float* pts = (const float*)d_in[0];
    (void)in_sizes; (void)n_in; (void)out_size;
    k_fused<<<NBLK, TPB>>>(pts, (float*)d_out);
}

// round 14
// speedup vs baseline: 1.1875x; 1.1875x over previous
#include <cuda_runtime.h>

// cosine_regularizer: out = (sum(W) - N)/N^2, W = p p^T, p = row-normalized points.
// Identity: sum(W) = || sum_i p_i ||^2.
// R14: split (R9 best-tied). k_fin launched with grid=148 (blocks 1..147 exit at once)
//      to defeat the documented low-grid issue throttle (vanishes @grid>=148).
//      g_rep transposed to [D][NREP]: k_fin reads 16 replicas as 4x LDG.128.

constexpr int N_ROWS = 16384;
constexpr int D      = 256;
constexpr int TPB    = 256;                 // 8 warps
constexpr int WARPS  = TPB / 32;
constexpr int NBLK   = 512;                 // 512*8 warps * 4 rows = 16384 rows
constexpr int ROWS_PER_WARP = 4;
constexpr int NREP   = 16;                  // column-sum replicas (R6 win)

__device__ float g_rep[D][NREP];   // transposed: column-major replicas, 64B per column

__global__ void __launch_bounds__(TPB, 3)
k_stream(const float* __restrict__ pts) {
    const int warp = threadIdx.x >> 5;
    const int lane = threadIdx.x & 31;
    const int t    = threadIdx.x;
    const int gw   = blockIdx.x * WARPS + warp;

    // Batch-issue all 8 LDG.128 for this warp's 4 rows.
    float4 v0[ROWS_PER_WARP], v1[ROWS_PER_WARP];
#pragma unroll
    for (int k = 0; k < ROWS_PER_WARP; k++) {
        const int row = gw + k * (NBLK * WARPS);
        const float4* p = reinterpret_cast<const float4*>(pts) + (size_t)row * (D / 4);
        v0[k] = p[lane];        // cols 4*lane   .. +3
        v1[k] = p[32 + lane];   // cols 128+4*lane .. +3
    }

    // Per-row sum of squares; 4 interleaved warp reductions.
    float ss[ROWS_PER_WARP];
#pragma unroll
    for (int k = 0; k < ROWS_PER_WARP; k++) {
        ss[k] = v0[k].x * v0[k].x + v0[k].y * v0[k].y + v0[k].z * v0[k].z + v0[k].w * v0[k].w
              + v1[k].x * v1[k].x + v1[k].y * v1[k].y + v1[k].z * v1[k].z + v1[k].w * v1[k].w;
    }
#pragma unroll
    for (int off = 16; off > 0; off >>= 1) {
#pragma unroll
        for (int k = 0; k < ROWS_PER_WARP; k++)
            ss[k] += __shfl_xor_sync(0xffffffffu, ss[k], off);
    }

    // rnorm * row into per-lane column accumulators.
    float4 a0 = make_float4(0.f, 0.f, 0.f, 0.f);
    float4 a1 = make_float4(0.f, 0.f, 0.f, 0.f);
#pragma unroll
    for (int k = 0; k < ROWS_PER_WARP; k++) {
        const float rn = rsqrtf(ss[k]);
        a0.x += rn * v0[k].x;  a0.y += rn * v0[k].y;
        a0.z += rn * v0[k].z;  a0.w += rn * v0[k].w;
        a1.x += rn * v1[k].x;  a1.y += rn * v1[k].y;
        a1.z += rn * v1[k].z;  a1.w += rn * v1[k].w;
    }

    // Block-reduce 8 warps' column partials via shared.
    __shared__ float sh[WARPS][D];
    float4* shv = reinterpret_cast<float4*>(sh[warp]);
    shv[lane]      = a0;
    shv[32 + lane] = a1;
    __syncthreads();

    float s = sh[0][t];
#pragma unroll
    for (int w = 1; w < WARPS; w++) s += sh[w][t];

    // Fire-and-forget RED into this block's replica slot (32 adds/address chip-wide).
    atomicAdd(&g_rep[t][blockIdx.x & (NREP - 1)], s);
}

__global__ void __launch_bounds__(TPB)
k_fin(float* __restrict__ out) {
    // Blocks 1..147 exist only to keep the grid above the low-grid throttle knee.
    if (blockIdx.x != 0) return;

    const int t    = threadIdx.x;
    const int warp = t >> 5;
    const int lane = t & 31;

    // This column's 16 replicas are 64 contiguous bytes: 4x LDG.128, one trip.
    const float4* rp = reinterpret_cast<const float4*>(&g_rep[t][0]);
    float4 r0 = __ldcg(rp + 0);
    float4 r1 = __ldcg(rp + 1);
    float4 r2 = __ldcg(rp + 2);
    float4 r3 = __ldcg(rp + 3);

    // Reset replicas for the next graph replay.
    float4* wp = reinterpret_cast<float4*>(&g_rep[t][0]);
    const float4 z = make_float4(0.f, 0.f, 0.f, 0.f);
    wp[0] = z; wp[1] = z; wp[2] = z; wp[3] = z;

    const float v = (r0.x + r0.y + r0.z + r0.w) + (r1.x + r1.y + r1.z + r1.w)
                  + (r2.x + r2.y + r2.z + r2.w) + (r3.x + r3.y + r3.z + r3.w);

    double d = (double)v * (double)v;
#pragma unroll
    for (int off = 16; off > 0; off >>= 1)
        d += __shfl_xor_sync(0xffffffffu, d, off);

    __shared__ double wsum[WARPS];
    if (lane == 0) wsum[warp] = d;
    __syncthreads();
    if (warp == 0) {
        double x = (lane < WARPS) ? wsum[lane] : 0.0;
#pragma unroll
        for (int off = 4; off > 0; off >>= 1)
            x += __shfl_xor_sync(0xffffffffu, x, off);
        if (lane == 0) {
            const double n = (double)N_ROWS;
            out[0] = (float)((x - n) / (n * n));
        }
    }
}

extern "C" void kernel_launch(void* const* d_in, const int* in_sizes, int n_in,
                              void* d_out, int out_size) {
    const float* pts = (const float*)d_in[0];
    (void)in_sizes; (void)n_in; (void)out_size;
    k_stream<<<NBLK, TPB>>>(pts);
    k_fin<<<148, TPB>>>((float*)d_out);
}